// round 11
// baseline (speedup 1.0000x reference)
#include <cuda_runtime.h>

#define NW 6
#define NL 4
#define HP 112
#define WP 112
#define NB 8
#define OC 16
#define NPIX (NB*HP*WP)

__device__ float g_y[NB*OC*HP*WP];

typedef unsigned long long ull;

__device__ __forceinline__ ull pk2(float lo, float hi) {
    ull r; asm("mov.b64 %0, {%1, %2};" : "=l"(r) : "f"(lo), "f"(hi)); return r;
}
__device__ __forceinline__ void upk2(ull v, float& lo, float& hi) {
    asm("mov.b64 {%0, %1}, %2;" : "=f"(lo), "=f"(hi) : "l"(v));
}
__device__ __forceinline__ ull fma2(ull a, ull b, ull c) {
    ull d; asm("fma.rn.f32x2 %0, %1, %2, %3;" : "=l"(d) : "l"(a), "l"(b), "l"(c)); return d;
}
__device__ __forceinline__ ull mul2(ull a, ull b) {
    ull d; asm("mul.rn.f32x2 %0, %1, %2;" : "=l"(d) : "l"(a), "l"(b)); return d;
}
__device__ __forceinline__ ull add2(ull a, ull b) {
    ull d; asm("add.rn.f32x2 %0, %1, %2;" : "=l"(d) : "l"(a), "l"(b)); return d;
}
__device__ __forceinline__ ull lds2(const float2& p) {
    return *reinterpret_cast<const ull*>(&p);
}

// ---------------------------------------------------------------------------
// Fused pixels kernel. PROLOGUE (per block, redundant, parallel): circuit sim
// (8 warps, register amplitudes + shuffles) -> M_w -> 27-term trig table,
// stored DUPLICATED as float2 for packed math. MAIN: two adjacent patch
// pixels per thread, all math in fma.rn.f32x2 (pixel0, pixel1) lanes.
// ---------------------------------------------------------------------------
__global__ void __launch_bounds__(256)
k_pixels(const float* __restrict__ x,
         const float* __restrict__ w,
         const float* __restrict__ fcw,
         const float* __restrict__ fcb,
         const float* __restrict__ lng,
         const float* __restrict__ lnb)
{
    __shared__ float2 sU[24][4];
    __shared__ float2 phi[8][65];
    __shared__ float  sD[4][64][13];
    __shared__ float  Mre[6][8][8];
    __shared__ float  Mim[6][8][8];
    __shared__ float2 sT2[162], sFC2[96], sFB2[16], sG2[16], sB2[16];

    const int tid  = threadIdx.x;          // 256 threads = 8 warps
    const int wrp  = tid >> 5;
    const int lane = tid & 31;
    const unsigned FULL = 0xFFFFFFFFu;

    if (tid < 96)  { const float v = fcw[tid]; sFC2[tid] = make_float2(v, v); }
    if (tid >= 96  && tid < 112) { const float v = fcb[tid - 96];  sFB2[tid - 96]  = make_float2(v, v); }
    if (tid >= 112 && tid < 128) { const float v = lng[tid - 112]; sG2[tid - 112] = make_float2(v, v); }
    if (tid >= 128 && tid < 144) { const float v = lnb[tid - 128]; sB2[tid - 128] = make_float2(v, v); }

    if (tid >= 160 && tid < 184) {
        const int gi = tid - 160;
        const float ph = w[gi*3 + 0];
        const float th = w[gi*3 + 1];
        const float om = w[gi*3 + 2];
        const float ch = cosf(0.5f * th), sh = sinf(0.5f * th);
        float cp, sp, cm, sm;
        sincosf(-0.5f * (ph + om), &sp, &cp);
        sincosf(-0.5f * (ph - om), &sm, &cm);
        sU[gi][0] = make_float2( cp*ch,  sp*ch);
        sU[gi][1] = make_float2(-cm*sh,  sm*sh);
        sU[gi][2] = make_float2( cm*sh,  sm*sh);
        sU[gi][3] = make_float2( cp*ch, -sp*ch);
    }
    __syncthreads();

    // ---- circuit: warp wrp simulates basis state |wrp>|000> ----
    {
        float ar = (lane == wrp * 8) ? 1.f : 0.f, ai = 0.f;
        float br = (lane + 32 == wrp * 8) ? 1.f : 0.f, bi = 0.f;

        for (int l = 0; l < NL; l++) {
            #pragma unroll
            for (int q = 0; q < NW; q++) {
                const float2 u00 = sU[l*6+q][0], u01 = sU[l*6+q][1];
                const float2 u10 = sU[l*6+q][2], u11 = sU[l*6+q][3];
                if (q == 0) {
                    const float nar = u00.x*ar - u00.y*ai + u01.x*br - u01.y*bi;
                    const float nai = u00.x*ai + u00.y*ar + u01.x*bi + u01.y*br;
                    const float nbr = u10.x*ar - u10.y*ai + u11.x*br - u11.y*bi;
                    const float nbi = u10.x*ai + u10.y*ar + u11.x*bi + u11.y*br;
                    ar = nar; ai = nai; br = nbr; bi = nbi;
                } else {
                    const int stride = 1 << (5 - q);
                    const float par = __shfl_xor_sync(FULL, ar, stride);
                    const float pai = __shfl_xor_sync(FULL, ai, stride);
                    const float pbr = __shfl_xor_sync(FULL, br, stride);
                    const float pbi = __shfl_xor_sync(FULL, bi, stride);
                    const bool hi = (lane & stride) != 0;
                    const float2 A  = hi ? u11 : u00;
                    const float2 Bc = hi ? u10 : u01;
                    {
                        const float nr = A.x*ar - A.y*ai + Bc.x*par - Bc.y*pai;
                        const float ni = A.x*ai + A.y*ar + Bc.x*pai + Bc.y*par;
                        ar = nr; ai = ni;
                    }
                    {
                        const float nr = A.x*br - A.y*bi + Bc.x*pbr - Bc.y*pbi;
                        const float ni = A.x*bi + A.y*br + Bc.x*pbi + Bc.y*pbr;
                        br = nr; bi = ni;
                    }
                }
            }
            const int r = l % (NW - 1) + 1;
            int i0 = lane, i1 = lane + 32;
            #pragma unroll
            for (int q = NW - 1; q >= 0; q--) {
                const int cpos = 5 - q;
                const int tpos = 5 - ((q + r) % NW);
                i0 ^= ((i0 >> cpos) & 1) << tpos;
                i1 ^= ((i1 >> cpos) & 1) << tpos;
            }
            const float g0ar = __shfl_sync(FULL, ar, i0 & 31);
            const float g0ai = __shfl_sync(FULL, ai, i0 & 31);
            const float g0br = __shfl_sync(FULL, br, i0 & 31);
            const float g0bi = __shfl_sync(FULL, bi, i0 & 31);
            const float g1ar = __shfl_sync(FULL, ar, i1 & 31);
            const float g1ai = __shfl_sync(FULL, ai, i1 & 31);
            const float g1br = __shfl_sync(FULL, br, i1 & 31);
            const float g1bi = __shfl_sync(FULL, bi, i1 & 31);
            ar = (i0 < 32) ? g0ar : g0br;
            ai = (i0 < 32) ? g0ai : g0bi;
            br = (i1 < 32) ? g1ar : g1br;
            bi = (i1 < 32) ? g1ai : g1bi;
        }
        phi[wrp][lane]      = make_float2(ar, ai);
        phi[wrp][lane + 32] = make_float2(br, bi);
    }
    __syncthreads();

    // ---- Phase D1: pair = tid&63 (fast), chunk = tid>>6 (slow) ----
    {
        const int pair = tid & 63, chunk = tid >> 6;
        const int i = pair >> 3, jj = pair & 7;
        const float s0 = (chunk & 2) ? -1.f : 1.f;
        const float s1 = (chunk & 1) ? -1.f : 1.f;
        float acc[12];
        #pragma unroll
        for (int m = 0; m < 12; m++) acc[m] = 0.f;
        #pragma unroll
        for (int k = 0; k < 16; k++) {
            const int t = chunk * 16 + k;
            const float2 a = phi[i][t], b = phi[jj][t];
            const float pre = a.x*b.x + a.y*b.y;
            const float pim = a.x*b.y - a.y*b.x;
            acc[0]  += pre;  acc[1]  += pim;
            acc[2]  += pre;  acc[3]  += pim;
            if (k & 8) { acc[4] -= pre; acc[5] -= pim; } else { acc[4] += pre; acc[5] += pim; }
            if (k & 4) { acc[6] -= pre; acc[7] -= pim; } else { acc[6] += pre; acc[7] += pim; }
            if (k & 2) { acc[8] -= pre; acc[9] -= pim; } else { acc[8] += pre; acc[9] += pim; }
            if (k & 1) { acc[10] -= pre; acc[11] -= pim; } else { acc[10] += pre; acc[11] += pim; }
        }
        acc[0] *= s0; acc[1] *= s0;
        acc[2] *= s1; acc[3] *= s1;
        #pragma unroll
        for (int m = 0; m < 12; m++) sD[chunk][pair][m] = acc[m];
    }
    __syncthreads();

    // ---- Phase D2: reduce 4 chunks -> Mre/Mim ----
    for (int o = tid; o < 768; o += 256) {
        const int c = o & 1, pair = (o >> 1) & 63, q = o >> 7;
        const float s = sD[0][pair][2*q+c] + sD[1][pair][2*q+c]
                      + sD[2][pair][2*q+c] + sD[3][pair][2*q+c];
        const int i = pair >> 3, jj = pair & 7;
        if (c) Mim[q][i][jj] = s; else Mre[q][i][jj] = s;
    }
    __syncthreads();

    // ---- Phase E: 8 contributing (i,jj) pairs per term -> sT2 (dup) ----
    if (tid < 6 * 27) {
        const int q = tid / 27, term = tid % 27;
        const int tt[3] = { term / 9, (term / 3) % 3, term % 3 };
        float acc = 0.f;
        #pragma unroll
        for (int k = 0; k < 8; k++) {
            int i = 0, jj = 0;
            float sgn = 0.125f;
            #pragma unroll
            for (int c = 0; c < 3; c++) {
                const int sel = (k >> c) & 1;
                const int t = tt[c];
                int bi, bj;
                if (t == 2) { bi = sel ^ 1; bj = sel; }
                else {
                    bi = sel; bj = sel;
                    if (t == 1 && sel == 1) sgn = -sgn;
                }
                i  |= bi << (2 - c);
                jj |= bj << (2 - c);
            }
            const int kph = (__popc(i) - __popc(jj)) & 3;
            const float mre = Mre[q][i][jj], mim = Mim[q][i][jj];
            const float f = (kph == 0) ? mre : (kph == 1) ? -mim
                          : (kph == 2) ? -mre : mim;
            acc += sgn * f;
        }
        sT2[tid] = make_float2(acc, acc);
    }
    __syncthreads();

    // ============ MAIN: two patch pixels per thread, packed f32x2 ==========
    const int pp = blockIdx.x * blockDim.x + tid;
    const int WPH = WP / 2;
    const int b   = pp / (HP * WPH);
    const int rem = pp % (HP * WPH);
    const int hp  = rem / WPH, wpp = rem % WPH;

    ull G[3][3];
    const ull ONE2 = 0x3f8000003f800000ULL;   // (1.f, 1.f)
    #pragma unroll
    for (int c = 0; c < 3; c++) {
        const float* base = x + (((long)(b * 3 + c) * 224 + 2 * hp) * 224 + 4 * wpp);
        const float4 r0 = *reinterpret_cast<const float4*>(base);
        const float4 r1 = *reinterpret_cast<const float4*>(base + 224);
        const float a0 = 0.25f * (r0.x + r0.y + r1.x + r1.y);
        const float a1 = 0.25f * (r0.z + r0.w + r1.z + r1.w);
        float sn0, cs0, sn1, cs1;
        __sincosf(a0, &sn0, &cs0);
        __sincosf(a1, &sn1, &cs1);
        G[c][0] = ONE2;
        G[c][1] = pk2(cs0, cs1);
        G[c][2] = pk2(sn0, sn1);
    }

    ull e2[6];
    #pragma unroll
    for (int q = 0; q < 6; q++) e2[q] = 0ULL;
    #pragma unroll
    for (int t0 = 0; t0 < 3; t0++)
        #pragma unroll
        for (int t1 = 0; t1 < 3; t1++) {
            const ull p01 = mul2(G[0][t0], G[1][t1]);
            #pragma unroll
            for (int t2 = 0; t2 < 3; t2++) {
                const ull bas = mul2(p01, G[2][t2]);
                const int t = (t0 * 3 + t1) * 3 + t2;
                #pragma unroll
                for (int q = 0; q < 6; q++)
                    e2[q] = fma2(lds2(sT2[q * 27 + t]), bas, e2[q]);
            }
        }

    const ull C_1_16 = pk2(0.0625f, 0.0625f);
    const ull C_M1   = pk2(-1.f, -1.f);
    ull y2[OC], mu2 = 0ULL;
    #pragma unroll
    for (int o = 0; o < OC; o++) {
        ull acc = lds2(sFB2[o]);
        #pragma unroll
        for (int q = 0; q < 6; q++) acc = fma2(lds2(sFC2[o * 6 + q]), e2[q], acc);
        y2[o] = acc;
        mu2 = add2(mu2, acc);
    }
    mu2 = mul2(mu2, C_1_16);
    ull var2 = 0ULL;
    #pragma unroll
    for (int o = 0; o < OC; o++) {
        y2[o] = fma2(mu2, C_M1, y2[o]);          // y - mu
        var2 = fma2(y2[o], y2[o], var2);
    }
    var2 = mul2(var2, C_1_16);
    float v0, v1;
    upk2(var2, v0, v1);
    const ull inv2 = pk2(rsqrtf(v0 + 1e-5f), rsqrtf(v1 + 1e-5f));

    float* yout = &g_y[(((long)b * OC) * HP + hp) * WP + 2 * wpp];
    #pragma unroll
    for (int o = 0; o < OC; o++) {
        const ull t = mul2(y2[o], inv2);
        const ull v = fma2(t, lds2(sG2[o]), lds2(sB2[o]));
        float a, c;
        upk2(v, a, c);
        *reinterpret_cast<float2*>(yout + (long)o * HP * WP) =
            make_float2(fmaxf(a, 0.f), fmaxf(c, 0.f));
    }
}

// ---------------------------------------------------------------------------
// Kernel 2 (v4): 2x bilinear upsample, register gather, 2x8 outputs/thread.
// 9 LDG (middle 4 input cols = one float4) -> 16 outputs via 4 STG.128.
// jax half-pixel weights with clamped edges.
// ---------------------------------------------------------------------------
__global__ void __launch_bounds__(256)
k_resize(float* __restrict__ out)
{
    const int idx = blockIdx.x * 256 + threadIdx.x;   // 1568 blocks exactly
    const int gc = idx % 28;                          // 8-col output group
    const int m  = (idx / 28) % HP;                   // input row
    const int pl = idx / (28 * HP);                   // (b, oc) plane
    const float* yb = g_y + (long)pl * HP * WP;

    const int rm = max(m - 1, 0), rp = min(m + 1, HP - 1);
    const int c0 = 4 * gc;
    const int cm = max(c0 - 1, 0), c4i = min(c0 + 4, WP - 1);

    float hv[3][8];
    const int rows[3] = { rm, m, rp };
    #pragma unroll
    for (int r = 0; r < 3; r++) {
        const float* rowp = yb + rows[r] * WP;
        const float  vm1 = __ldg(rowp + cm);
        const float4 v   = *reinterpret_cast<const float4*>(rowp + c0);
        const float  v4  = __ldg(rowp + c4i);
        hv[r][0] = 0.25f * vm1 + 0.75f * v.x;
        hv[r][1] = 0.75f * v.x + 0.25f * v.y;
        hv[r][2] = 0.25f * v.x + 0.75f * v.y;
        hv[r][3] = 0.75f * v.y + 0.25f * v.z;
        hv[r][4] = 0.25f * v.y + 0.75f * v.z;
        hv[r][5] = 0.75f * v.z + 0.25f * v.w;
        hv[r][6] = 0.25f * v.z + 0.75f * v.w;
        hv[r][7] = 0.75f * v.w + 0.25f * v4;
    }

    float* obase = out + (((long)pl * 224 + 2 * m) * 224 + 8 * gc);
    *reinterpret_cast<float4*>(obase) = make_float4(
        0.25f * hv[0][0] + 0.75f * hv[1][0],
        0.25f * hv[0][1] + 0.75f * hv[1][1],
        0.25f * hv[0][2] + 0.75f * hv[1][2],
        0.25f * hv[0][3] + 0.75f * hv[1][3]);
    *reinterpret_cast<float4*>(obase + 4) = make_float4(
        0.25f * hv[0][4] + 0.75f * hv[1][4],
        0.25f * hv[0][5] + 0.75f * hv[1][5],
        0.25f * hv[0][6] + 0.75f * hv[1][6],
        0.25f * hv[0][7] + 0.75f * hv[1][7]);
    *reinterpret_cast<float4*>(obase + 224) = make_float4(
        0.75f * hv[1][0] + 0.25f * hv[2][0],
        0.75f * hv[1][1] + 0.25f * hv[2][1],
        0.75f * hv[1][2] + 0.25f * hv[2][2],
        0.75f * hv[1][3] + 0.25f * hv[2][3]);
    *reinterpret_cast<float4*>(obase + 228) = make_float4(
        0.75f * hv[1][4] + 0.25f * hv[2][4],
        0.75f * hv[1][5] + 0.25f * hv[2][5],
        0.75f * hv[1][6] + 0.25f * hv[2][6],
        0.75f * hv[1][7] + 0.25f * hv[2][7]);
}

extern "C" void kernel_launch(void* const* d_in, const int* in_sizes, int n_in,
                              void* d_out, int out_size)
{
    const float* x   = (const float*)d_in[0];
    const float* wts = (const float*)d_in[1];
    const float* fcw = (const float*)d_in[2];
    const float* fcb = (const float*)d_in[3];
    const float* lng = (const float*)d_in[4];
    const float* lnb = (const float*)d_in[5];
    float* out = (float*)d_out;

    k_pixels<<<NPIX / 2 / 256, 256>>>(x, wts, fcw, fcb, lng, lnb);
    k_resize<<<(28 * HP * NB * OC) / 256, 256>>>(out);
}

// round 12
// speedup vs baseline: 1.5831x; 1.5831x over previous
#include <cuda_runtime.h>

#define NW 6
#define NL 4
#define HP 112
#define WP 112
#define NB 8
#define OC 16
#define NPIX (NB*HP*WP)

__device__ float g_T[162];
__device__ float g_y[NB*OC*HP*WP];

// ---------------------------------------------------------------------------
// Kernel 0 (table): grid=148 blocks ALL redundantly compute the 27-term trig
// table (identical values) and store to g_T. Avoids both the single-CTA
// low-grid throttle (needs grid>=148) and paying the prologue chain in every
// pixel block. Circuit: 8 warps, register amplitudes + shuffles; CNOT ring
// folded to one index permutation per layer.
// ---------------------------------------------------------------------------
__global__ void __launch_bounds__(256)
k_table(const float* __restrict__ w)
{
    __shared__ float2 sU[24][4];
    __shared__ float2 phi[8][65];
    __shared__ float  sD[4][64][13];
    __shared__ float  Mre[6][8][8];
    __shared__ float  Mim[6][8][8];

    const int tid  = threadIdx.x;          // 256 threads = 8 warps
    const int wrp  = tid >> 5;
    const int lane = tid & 31;
    const unsigned FULL = 0xFFFFFFFFu;

    if (tid < 24) {
        const float ph = w[tid*3 + 0];
        const float th = w[tid*3 + 1];
        const float om = w[tid*3 + 2];
        const float ch = cosf(0.5f * th), sh = sinf(0.5f * th);
        float cp, sp, cm, sm;
        sincosf(-0.5f * (ph + om), &sp, &cp);
        sincosf(-0.5f * (ph - om), &sm, &cm);
        sU[tid][0] = make_float2( cp*ch,  sp*ch);
        sU[tid][1] = make_float2(-cm*sh,  sm*sh);
        sU[tid][2] = make_float2( cm*sh,  sm*sh);
        sU[tid][3] = make_float2( cp*ch, -sp*ch);
    }
    __syncthreads();

    // ---- circuit: warp wrp simulates basis state |wrp>|000> ----
    {
        float ar = (lane == wrp * 8) ? 1.f : 0.f, ai = 0.f;
        float br = (lane + 32 == wrp * 8) ? 1.f : 0.f, bi = 0.f;

        for (int l = 0; l < NL; l++) {
            #pragma unroll
            for (int q = 0; q < NW; q++) {
                const float2 u00 = sU[l*6+q][0], u01 = sU[l*6+q][1];
                const float2 u10 = sU[l*6+q][2], u11 = sU[l*6+q][3];
                if (q == 0) {
                    const float nar = u00.x*ar - u00.y*ai + u01.x*br - u01.y*bi;
                    const float nai = u00.x*ai + u00.y*ar + u01.x*bi + u01.y*br;
                    const float nbr = u10.x*ar - u10.y*ai + u11.x*br - u11.y*bi;
                    const float nbi = u10.x*ai + u10.y*ar + u11.x*bi + u11.y*br;
                    ar = nar; ai = nai; br = nbr; bi = nbi;
                } else {
                    const int stride = 1 << (5 - q);
                    const float par = __shfl_xor_sync(FULL, ar, stride);
                    const float pai = __shfl_xor_sync(FULL, ai, stride);
                    const float pbr = __shfl_xor_sync(FULL, br, stride);
                    const float pbi = __shfl_xor_sync(FULL, bi, stride);
                    const bool hi = (lane & stride) != 0;
                    const float2 A  = hi ? u11 : u00;
                    const float2 Bc = hi ? u10 : u01;
                    {
                        const float nr = A.x*ar - A.y*ai + Bc.x*par - Bc.y*pai;
                        const float ni = A.x*ai + A.y*ar + Bc.x*pai + Bc.y*par;
                        ar = nr; ai = ni;
                    }
                    {
                        const float nr = A.x*br - A.y*bi + Bc.x*pbr - Bc.y*pbi;
                        const float ni = A.x*bi + A.y*br + Bc.x*pbi + Bc.y*pbr;
                        br = nr; bi = ni;
                    }
                }
            }
            const int r = l % (NW - 1) + 1;
            int i0 = lane, i1 = lane + 32;
            #pragma unroll
            for (int q = NW - 1; q >= 0; q--) {
                const int cpos = 5 - q;
                const int tpos = 5 - ((q + r) % NW);
                i0 ^= ((i0 >> cpos) & 1) << tpos;
                i1 ^= ((i1 >> cpos) & 1) << tpos;
            }
            const float g0ar = __shfl_sync(FULL, ar, i0 & 31);
            const float g0ai = __shfl_sync(FULL, ai, i0 & 31);
            const float g0br = __shfl_sync(FULL, br, i0 & 31);
            const float g0bi = __shfl_sync(FULL, bi, i0 & 31);
            const float g1ar = __shfl_sync(FULL, ar, i1 & 31);
            const float g1ai = __shfl_sync(FULL, ai, i1 & 31);
            const float g1br = __shfl_sync(FULL, br, i1 & 31);
            const float g1bi = __shfl_sync(FULL, bi, i1 & 31);
            ar = (i0 < 32) ? g0ar : g0br;
            ai = (i0 < 32) ? g0ai : g0bi;
            br = (i1 < 32) ? g1ar : g1br;
            bi = (i1 < 32) ? g1ai : g1bi;
        }
        phi[wrp][lane]      = make_float2(ar, ai);
        phi[wrp][lane + 32] = make_float2(br, bi);
    }
    __syncthreads();

    // ---- Phase D1: pair = tid&63 (fast), chunk = tid>>6 (slow) ----
    {
        const int pair = tid & 63, chunk = tid >> 6;
        const int i = pair >> 3, jj = pair & 7;
        const float s0 = (chunk & 2) ? -1.f : 1.f;
        const float s1 = (chunk & 1) ? -1.f : 1.f;
        float acc[12];
        #pragma unroll
        for (int m = 0; m < 12; m++) acc[m] = 0.f;
        #pragma unroll
        for (int k = 0; k < 16; k++) {
            const int t = chunk * 16 + k;
            const float2 a = phi[i][t], b = phi[jj][t];
            const float pre = a.x*b.x + a.y*b.y;
            const float pim = a.x*b.y - a.y*b.x;
            acc[0]  += pre;  acc[1]  += pim;
            acc[2]  += pre;  acc[3]  += pim;
            if (k & 8) { acc[4] -= pre; acc[5] -= pim; } else { acc[4] += pre; acc[5] += pim; }
            if (k & 4) { acc[6] -= pre; acc[7] -= pim; } else { acc[6] += pre; acc[7] += pim; }
            if (k & 2) { acc[8] -= pre; acc[9] -= pim; } else { acc[8] += pre; acc[9] += pim; }
            if (k & 1) { acc[10] -= pre; acc[11] -= pim; } else { acc[10] += pre; acc[11] += pim; }
        }
        acc[0] *= s0; acc[1] *= s0;
        acc[2] *= s1; acc[3] *= s1;
        #pragma unroll
        for (int m = 0; m < 12; m++) sD[chunk][pair][m] = acc[m];
    }
    __syncthreads();

    // ---- Phase D2: reduce 4 chunks -> Mre/Mim ----
    for (int o = tid; o < 768; o += 256) {
        const int c = o & 1, pair = (o >> 1) & 63, q = o >> 7;
        const float s = sD[0][pair][2*q+c] + sD[1][pair][2*q+c]
                      + sD[2][pair][2*q+c] + sD[3][pair][2*q+c];
        const int i = pair >> 3, jj = pair & 7;
        if (c) Mim[q][i][jj] = s; else Mre[q][i][jj] = s;
    }
    __syncthreads();

    // ---- Phase E: 8 contributing (i,jj) pairs per term -> g_T ----
    if (tid < 6 * 27) {
        const int q = tid / 27, term = tid % 27;
        const int tt[3] = { term / 9, (term / 3) % 3, term % 3 };
        float acc = 0.f;
        #pragma unroll
        for (int k = 0; k < 8; k++) {
            int i = 0, jj = 0;
            float sgn = 0.125f;
            #pragma unroll
            for (int c = 0; c < 3; c++) {
                const int sel = (k >> c) & 1;
                const int t = tt[c];
                int bi, bj;
                if (t == 2) { bi = sel ^ 1; bj = sel; }
                else {
                    bi = sel; bj = sel;
                    if (t == 1 && sel == 1) sgn = -sgn;
                }
                i  |= bi << (2 - c);
                jj |= bj << (2 - c);
            }
            const int kph = (__popc(i) - __popc(jj)) & 3;
            const float mre = Mre[q][i][jj], mim = Mim[q][i][jj];
            const float f = (kph == 0) ? mre : (kph == 1) ? -mim
                          : (kph == 2) ? -mre : mim;
            acc += sgn * f;
        }
        g_T[tid] = acc;   // all blocks write identical values — benign
    }
}

// ---------------------------------------------------------------------------
// Kernel 1: main pixels only (table read from g_T). Two adjacent patch
// pixels per thread: 2x2 mean (float4) -> fast sincos -> trig basis ->
// 6 exps -> FC -> LayerNorm -> ReLU -> g_y (float2 per channel).
// ---------------------------------------------------------------------------
__global__ void __launch_bounds__(256)
k_pixels(const float* __restrict__ x,
         const float* __restrict__ fcw,
         const float* __restrict__ fcb,
         const float* __restrict__ lng,
         const float* __restrict__ lnb)
{
    __shared__ float sT[162], sFC[96], sFB[16], sG[16], sB[16];
    const int tid = threadIdx.x;
    if (tid < 162) sT[tid] = g_T[tid];
    if (tid < 96)  sFC[tid] = fcw[tid];
    if (tid >= 96  && tid < 112) sFB[tid - 96]  = fcb[tid - 96];
    if (tid >= 112 && tid < 128) sG [tid - 112] = lng[tid - 112];
    if (tid >= 128 && tid < 144) sB [tid - 128] = lnb[tid - 128];
    __syncthreads();

    const int pp = blockIdx.x * blockDim.x + tid;   // grid sized exactly
    const int WPH = WP / 2;
    const int b   = pp / (HP * WPH);
    const int rem = pp % (HP * WPH);
    const int hp  = rem / WPH, wpp = rem % WPH;

    float g0[3][3], g1[3][3];
    #pragma unroll
    for (int c = 0; c < 3; c++) {
        const float* base = x + (((long)(b * 3 + c) * 224 + 2 * hp) * 224 + 4 * wpp);
        const float4 r0 = *reinterpret_cast<const float4*>(base);
        const float4 r1 = *reinterpret_cast<const float4*>(base + 224);
        const float a0 = 0.25f * (r0.x + r0.y + r1.x + r1.y);
        const float a1 = 0.25f * (r0.z + r0.w + r1.z + r1.w);
        float sn, cs;
        __sincosf(a0, &sn, &cs);
        g0[c][0] = 1.f; g0[c][1] = cs; g0[c][2] = sn;
        __sincosf(a1, &sn, &cs);
        g1[c][0] = 1.f; g1[c][1] = cs; g1[c][2] = sn;
    }

    float2 vout[OC];
    #pragma unroll
    for (int half = 0; half < 2; half++) {
        float (*gg)[3] = half ? g1 : g0;

        float e[6];
        #pragma unroll
        for (int q = 0; q < 6; q++) e[q] = 0.f;
        #pragma unroll
        for (int t0 = 0; t0 < 3; t0++)
            #pragma unroll
            for (int t1 = 0; t1 < 3; t1++) {
                const float p01 = gg[0][t0] * gg[1][t1];
                #pragma unroll
                for (int t2 = 0; t2 < 3; t2++) {
                    const float bas = p01 * gg[2][t2];
                    const int t = (t0 * 3 + t1) * 3 + t2;
                    #pragma unroll
                    for (int q = 0; q < 6; q++) e[q] += sT[q * 27 + t] * bas;
                }
            }

        float y[OC], mu = 0.f;
        #pragma unroll
        for (int o = 0; o < OC; o++) {
            float acc = sFB[o];
            #pragma unroll
            for (int q = 0; q < 6; q++) acc += sFC[o * 6 + q] * e[q];
            y[o] = acc;
            mu += acc;
        }
        mu *= (1.f / OC);
        float var = 0.f;
        #pragma unroll
        for (int o = 0; o < OC; o++) { const float d = y[o] - mu; var += d * d; }
        var *= (1.f / OC);
        const float inv = rsqrtf(var + 1e-5f);
        #pragma unroll
        for (int o = 0; o < OC; o++) {
            const float v = fmaxf((y[o] - mu) * inv * sG[o] + sB[o], 0.f);
            if (half) vout[o].y = v; else vout[o].x = v;
        }
    }

    #pragma unroll
    for (int o = 0; o < OC; o++) {
        *reinterpret_cast<float2*>(
            &g_y[(((long)b * OC + o) * HP + hp) * WP + 2 * wpp]) = vout[o];
    }
}

// ---------------------------------------------------------------------------
// Kernel 2 (R10 version): 2x bilinear upsample, pure register gather.
// One thread = 2 output rows x 4 output cols. 9 LDG (middle pair as aligned
// float2), ~56 FMA, 2 STG.128. jax half-pixel weights, clamped edges.
// ---------------------------------------------------------------------------
__global__ void __launch_bounds__(256)
k_resize(float* __restrict__ out)
{
    const int idx = blockIdx.x * 256 + threadIdx.x;   // 3136 blocks exactly
    const int c4 = idx % 56;                          // 4-col output group
    const int m  = (idx / 56) % HP;                   // input row
    const int pl = idx / (56 * HP);                   // (b, oc) plane
    const float* yb = g_y + (long)pl * HP * WP;

    const int rm = max(m - 1, 0), rp = min(m + 1, HP - 1);
    const int c0 = 2 * c4;
    const int cm = max(c0 - 1, 0), c2 = min(c0 + 2, WP - 1);

    float hA[3], hB[3], hC[3], hD[3];
    const int rows[3] = { rm, m, rp };
    #pragma unroll
    for (int r = 0; r < 3; r++) {
        const float* rowp = yb + rows[r] * WP;
        const float  vm1 = __ldg(rowp + cm);
        const float2 v01 = *reinterpret_cast<const float2*>(rowp + c0);
        const float  v2  = __ldg(rowp + c2);
        hA[r] = 0.25f * vm1   + 0.75f * v01.x;
        hB[r] = 0.75f * v01.x + 0.25f * v01.y;
        hC[r] = 0.25f * v01.x + 0.75f * v01.y;
        hD[r] = 0.75f * v01.y + 0.25f * v2;
    }

    float* obase = out + (((long)pl * 224 + 2 * m) * 224 + 4 * c4);
    *reinterpret_cast<float4*>(obase) = make_float4(
        0.25f * hA[0] + 0.75f * hA[1],
        0.25f * hB[0] + 0.75f * hB[1],
        0.25f * hC[0] + 0.75f * hC[1],
        0.25f * hD[0] + 0.75f * hD[1]);
    *reinterpret_cast<float4*>(obase + 224) = make_float4(
        0.75f * hA[1] + 0.25f * hA[2],
        0.75f * hB[1] + 0.25f * hB[2],
        0.75f * hC[1] + 0.25f * hC[2],
        0.75f * hD[1] + 0.25f * hD[2]);
}

extern "C" void kernel_launch(void* const* d_in, const int* in_sizes, int n_in,
                              void* d_out, int out_size)
{
    const float* x   = (const float*)d_in[0];
    const float* wts = (const float*)d_in[1];
    const float* fcw = (const float*)d_in[2];
    const float* fcb = (const float*)d_in[3];
    const float* lng = (const float*)d_in[4];
    const float* lnb = (const float*)d_in[5];
    float* out = (float*)d_out;

    k_table<<<148, 256>>>(wts);
    k_pixels<<<NPIX / 2 / 256, 256>>>(x, fcw, fcb, lng, lnb);
    k_resize<<<(56 * HP * NB * OC) / 256, 256>>>(out);
}

// round 13
// speedup vs baseline: 1.7496x; 1.1052x over previous
#include <cuda_runtime.h>

#define NW 6
#define NL 4
#define HP 112
#define WP 112
#define NB 8
#define OC 16
#define NPIX (NB*HP*WP)

__device__ float g_y[NB*OC*HP*WP];

// ---------------------------------------------------------------------------
// Fused pixels kernel (R10 structure + hoisted x loads).
// x loads issue FIRST (independent of prologue; their DRAM latency hides
// behind the prologue chain). PROLOGUE (per block, redundant, parallel):
// circuit sim -> M_w -> 27-term trig table sT. MAIN: two adjacent patch
// pixels per thread.
// ---------------------------------------------------------------------------
__global__ void __launch_bounds__(256)
k_pixels(const float* __restrict__ x,
         const float* __restrict__ w,
         const float* __restrict__ fcw,
         const float* __restrict__ fcb,
         const float* __restrict__ lng,
         const float* __restrict__ lnb)
{
    __shared__ float2 sU[24][4];
    __shared__ float2 phi[8][65];
    __shared__ float  sD[4][64][13];
    __shared__ float  Mre[6][8][8];
    __shared__ float  Mim[6][8][8];
    __shared__ float  sT[162], sFC[96], sFB[16], sG[16], sB[16];

    const int tid  = threadIdx.x;          // 256 threads = 8 warps
    const int wrp  = tid >> 5;
    const int lane = tid & 31;
    const unsigned FULL = 0xFFFFFFFFu;

    // ---- hoisted x loads (independent of prologue) ----
    const int pp = blockIdx.x * blockDim.x + tid;
    const int WPH = WP / 2;
    const int b   = pp / (HP * WPH);
    const int rem = pp % (HP * WPH);
    const int hp  = rem / WPH, wpp = rem % WPH;
    float4 xr0[3], xr1[3];
    #pragma unroll
    for (int c = 0; c < 3; c++) {
        const float* base = x + (((long)(b * 3 + c) * 224 + 2 * hp) * 224 + 4 * wpp);
        xr0[c] = *reinterpret_cast<const float4*>(base);
        xr1[c] = *reinterpret_cast<const float4*>(base + 224);
    }

    // ---- param staging ----
    if (tid < 96)  sFC[tid] = fcw[tid];
    if (tid >= 96  && tid < 112) sFB[tid - 96]  = fcb[tid - 96];
    if (tid >= 112 && tid < 128) sG [tid - 112] = lng[tid - 112];
    if (tid >= 128 && tid < 144) sB [tid - 128] = lnb[tid - 128];

    if (tid >= 160 && tid < 184) {
        const int gi = tid - 160;
        const float ph = w[gi*3 + 0];
        const float th = w[gi*3 + 1];
        const float om = w[gi*3 + 2];
        const float ch = cosf(0.5f * th), sh = sinf(0.5f * th);
        float cp, sp, cm, sm;
        sincosf(-0.5f * (ph + om), &sp, &cp);
        sincosf(-0.5f * (ph - om), &sm, &cm);
        sU[gi][0] = make_float2( cp*ch,  sp*ch);
        sU[gi][1] = make_float2(-cm*sh,  sm*sh);
        sU[gi][2] = make_float2( cm*sh,  sm*sh);
        sU[gi][3] = make_float2( cp*ch, -sp*ch);
    }
    __syncthreads();

    // ---- circuit: warp wrp simulates basis state |wrp>|000> ----
    {
        float ar = (lane == wrp * 8) ? 1.f : 0.f, ai = 0.f;
        float br = (lane + 32 == wrp * 8) ? 1.f : 0.f, bi = 0.f;

        for (int l = 0; l < NL; l++) {
            #pragma unroll
            for (int q = 0; q < NW; q++) {
                const float2 u00 = sU[l*6+q][0], u01 = sU[l*6+q][1];
                const float2 u10 = sU[l*6+q][2], u11 = sU[l*6+q][3];
                if (q == 0) {
                    const float nar = u00.x*ar - u00.y*ai + u01.x*br - u01.y*bi;
                    const float nai = u00.x*ai + u00.y*ar + u01.x*bi + u01.y*br;
                    const float nbr = u10.x*ar - u10.y*ai + u11.x*br - u11.y*bi;
                    const float nbi = u10.x*ai + u10.y*ar + u11.x*bi + u11.y*br;
                    ar = nar; ai = nai; br = nbr; bi = nbi;
                } else {
                    const int stride = 1 << (5 - q);
                    const float par = __shfl_xor_sync(FULL, ar, stride);
                    const float pai = __shfl_xor_sync(FULL, ai, stride);
                    const float pbr = __shfl_xor_sync(FULL, br, stride);
                    const float pbi = __shfl_xor_sync(FULL, bi, stride);
                    const bool hi = (lane & stride) != 0;
                    const float2 A  = hi ? u11 : u00;
                    const float2 Bc = hi ? u10 : u01;
                    {
                        const float nr = A.x*ar - A.y*ai + Bc.x*par - Bc.y*pai;
                        const float ni = A.x*ai + A.y*ar + Bc.x*pai + Bc.y*par;
                        ar = nr; ai = ni;
                    }
                    {
                        const float nr = A.x*br - A.y*bi + Bc.x*pbr - Bc.y*pbi;
                        const float ni = A.x*bi + A.y*br + Bc.x*pbi + Bc.y*pbr;
                        br = nr; bi = ni;
                    }
                }
            }
            const int r = l % (NW - 1) + 1;
            int i0 = lane, i1 = lane + 32;
            #pragma unroll
            for (int q = NW - 1; q >= 0; q--) {
                const int cpos = 5 - q;
                const int tpos = 5 - ((q + r) % NW);
                i0 ^= ((i0 >> cpos) & 1) << tpos;
                i1 ^= ((i1 >> cpos) & 1) << tpos;
            }
            const float g0ar = __shfl_sync(FULL, ar, i0 & 31);
            const float g0ai = __shfl_sync(FULL, ai, i0 & 31);
            const float g0br = __shfl_sync(FULL, br, i0 & 31);
            const float g0bi = __shfl_sync(FULL, bi, i0 & 31);
            const float g1ar = __shfl_sync(FULL, ar, i1 & 31);
            const float g1ai = __shfl_sync(FULL, ai, i1 & 31);
            const float g1br = __shfl_sync(FULL, br, i1 & 31);
            const float g1bi = __shfl_sync(FULL, bi, i1 & 31);
            ar = (i0 < 32) ? g0ar : g0br;
            ai = (i0 < 32) ? g0ai : g0bi;
            br = (i1 < 32) ? g1ar : g1br;
            bi = (i1 < 32) ? g1ai : g1bi;
        }
        phi[wrp][lane]      = make_float2(ar, ai);
        phi[wrp][lane + 32] = make_float2(br, bi);
    }
    __syncthreads();

    // ---- Phase D1: pair = tid&63 (fast), chunk = tid>>6 (slow) ----
    {
        const int pair = tid & 63, chunk = tid >> 6;
        const int i = pair >> 3, jj = pair & 7;
        const float s0 = (chunk & 2) ? -1.f : 1.f;
        const float s1 = (chunk & 1) ? -1.f : 1.f;
        float acc[12];
        #pragma unroll
        for (int m = 0; m < 12; m++) acc[m] = 0.f;
        #pragma unroll
        for (int k = 0; k < 16; k++) {
            const int t = chunk * 16 + k;
            const float2 a = phi[i][t], bb = phi[jj][t];
            const float pre = a.x*bb.x + a.y*bb.y;
            const float pim = a.x*bb.y - a.y*bb.x;
            acc[0]  += pre;  acc[1]  += pim;
            acc[2]  += pre;  acc[3]  += pim;
            if (k & 8) { acc[4] -= pre; acc[5] -= pim; } else { acc[4] += pre; acc[5] += pim; }
            if (k & 4) { acc[6] -= pre; acc[7] -= pim; } else { acc[6] += pre; acc[7] += pim; }
            if (k & 2) { acc[8] -= pre; acc[9] -= pim; } else { acc[8] += pre; acc[9] += pim; }
            if (k & 1) { acc[10] -= pre; acc[11] -= pim; } else { acc[10] += pre; acc[11] += pim; }
        }
        acc[0] *= s0; acc[1] *= s0;
        acc[2] *= s1; acc[3] *= s1;
        #pragma unroll
        for (int m = 0; m < 12; m++) sD[chunk][pair][m] = acc[m];
    }
    __syncthreads();

    // ---- Phase D2: reduce 4 chunks -> Mre/Mim ----
    for (int o = tid; o < 768; o += 256) {
        const int c = o & 1, pair = (o >> 1) & 63, q = o >> 7;
        const float s = sD[0][pair][2*q+c] + sD[1][pair][2*q+c]
                      + sD[2][pair][2*q+c] + sD[3][pair][2*q+c];
        const int i = pair >> 3, jj = pair & 7;
        if (c) Mim[q][i][jj] = s; else Mre[q][i][jj] = s;
    }
    __syncthreads();

    // ---- Phase E: 8 contributing (i,jj) pairs per term -> sT ----
    if (tid < 6 * 27) {
        const int q = tid / 27, term = tid % 27;
        const int tt[3] = { term / 9, (term / 3) % 3, term % 3 };
        float acc = 0.f;
        #pragma unroll
        for (int k = 0; k < 8; k++) {
            int i = 0, jj = 0;
            float sgn = 0.125f;
            #pragma unroll
            for (int c = 0; c < 3; c++) {
                const int sel = (k >> c) & 1;
                const int t = tt[c];
                int bi, bj;
                if (t == 2) { bi = sel ^ 1; bj = sel; }
                else {
                    bi = sel; bj = sel;
                    if (t == 1 && sel == 1) sgn = -sgn;
                }
                i  |= bi << (2 - c);
                jj |= bj << (2 - c);
            }
            const int kph = (__popc(i) - __popc(jj)) & 3;
            const float mre = Mre[q][i][jj], mim = Mim[q][i][jj];
            const float f = (kph == 0) ? mre : (kph == 1) ? -mim
                          : (kph == 2) ? -mre : mim;
            acc += sgn * f;
        }
        sT[tid] = acc;
    }
    __syncthreads();

    // ================== MAIN: two patch pixels per thread ==================
    float g0[3][3], g1[3][3];
    #pragma unroll
    for (int c = 0; c < 3; c++) {
        const float a0 = 0.25f * (xr0[c].x + xr0[c].y + xr1[c].x + xr1[c].y);
        const float a1 = 0.25f * (xr0[c].z + xr0[c].w + xr1[c].z + xr1[c].w);
        float sn, cs;
        __sincosf(a0, &sn, &cs);
        g0[c][0] = 1.f; g0[c][1] = cs; g0[c][2] = sn;
        __sincosf(a1, &sn, &cs);
        g1[c][0] = 1.f; g1[c][1] = cs; g1[c][2] = sn;
    }

    float2 vout[OC];
    #pragma unroll
    for (int half = 0; half < 2; half++) {
        float (*gg)[3] = half ? g1 : g0;

        float e[6];
        #pragma unroll
        for (int q = 0; q < 6; q++) e[q] = 0.f;
        #pragma unroll
        for (int t0 = 0; t0 < 3; t0++)
            #pragma unroll
            for (int t1 = 0; t1 < 3; t1++) {
                const float p01 = gg[0][t0] * gg[1][t1];
                #pragma unroll
                for (int t2 = 0; t2 < 3; t2++) {
                    const float bas = p01 * gg[2][t2];
                    const int t = (t0 * 3 + t1) * 3 + t2;
                    #pragma unroll
                    for (int q = 0; q < 6; q++) e[q] += sT[q * 27 + t] * bas;
                }
            }

        float y[OC], mu = 0.f;
        #pragma unroll
        for (int o = 0; o < OC; o++) {
            float acc = sFB[o];
            #pragma unroll
            for (int q = 0; q < 6; q++) acc += sFC[o * 6 + q] * e[q];
            y[o] = acc;
            mu += acc;
        }
        mu *= (1.f / OC);
        float var = 0.f;
        #pragma unroll
        for (int o = 0; o < OC; o++) { const float d = y[o] - mu; var += d * d; }
        var *= (1.f / OC);
        const float inv = rsqrtf(var + 1e-5f);
        #pragma unroll
        for (int o = 0; o < OC; o++) {
            const float v = fmaxf((y[o] - mu) * inv * sG[o] + sB[o], 0.f);
            if (half) vout[o].y = v; else vout[o].x = v;
        }
    }

    #pragma unroll
    for (int o = 0; o < OC; o++) {
        *reinterpret_cast<float2*>(
            &g_y[(((long)b * OC + o) * HP + hp) * WP + 2 * wpp]) = vout[o];
    }
}

// ---------------------------------------------------------------------------
// Kernel 2 (v5): 2x bilinear upsample, register gather, zero div/mod.
// block(56,4): c4 = threadIdx.x, m = blockIdx.x*4 + threadIdx.y,
// pl = blockIdx.y. Vertical blend first (16 FFMA), then horizontal
// (16 FFMA). 9 LDG, 2 STG.128 per thread (2x4 outputs).
// ---------------------------------------------------------------------------
__global__ void __launch_bounds__(224)
k_resize(float* __restrict__ out)
{
    const int c4 = threadIdx.x;                       // 0..55
    const int m  = blockIdx.x * 4 + threadIdx.y;      // input row
    const int pl = blockIdx.y;                        // (b, oc) plane
    const float* yb = g_y + (long)pl * HP * WP;

    const int rm = max(m - 1, 0), rp = min(m + 1, HP - 1);
    const int c0 = 2 * c4;
    const int cm = max(c0 - 1, 0), c2 = min(c0 + 2, WP - 1);

    // load 3 rows x 4 values
    float v[3][4];
    const int rows[3] = { rm, m, rp };
    #pragma unroll
    for (int r = 0; r < 3; r++) {
        const float* rowp = yb + rows[r] * WP;
        v[r][0] = __ldg(rowp + cm);
        const float2 mid = *reinterpret_cast<const float2*>(rowp + c0);
        v[r][1] = mid.x; v[r][2] = mid.y;
        v[r][3] = __ldg(rowp + c2);
    }

    // vertical blends: top output row uses (rm, m), bottom uses (m, rp)
    float vt[4], vb[4];
    #pragma unroll
    for (int c = 0; c < 4; c++) {
        vt[c] = 0.25f * v[0][c] + 0.75f * v[1][c];
        vb[c] = 0.75f * v[1][c] + 0.25f * v[2][c];
    }

    float* obase = out + (((long)pl * 224 + 2 * m) * 224 + 4 * c4);
    *reinterpret_cast<float4*>(obase) = make_float4(
        0.25f * vt[0] + 0.75f * vt[1],
        0.75f * vt[1] + 0.25f * vt[2],
        0.25f * vt[1] + 0.75f * vt[2],
        0.75f * vt[2] + 0.25f * vt[3]);
    *reinterpret_cast<float4*>(obase + 224) = make_float4(
        0.25f * vb[0] + 0.75f * vb[1],
        0.75f * vb[1] + 0.25f * vb[2],
        0.25f * vb[1] + 0.75f * vb[2],
        0.75f * vb[2] + 0.25f * vb[3]);
}

extern "C" void kernel_launch(void* const* d_in, const int* in_sizes, int n_in,
                              void* d_out, int out_size)
{
    const float* x   = (const float*)d_in[0];
    const float* wts = (const float*)d_in[1];
    const float* fcw = (const float*)d_in[2];
    const float* fcb = (const float*)d_in[3];
    const float* lng = (const float*)d_in[4];
    const float* lnb = (const float*)d_in[5];
    float* out = (float*)d_out;

    k_pixels<<<NPIX / 2 / 256, 256>>>(x, wts, fcw, fcb, lng, lnb);
    dim3 rb(56, 4);
    dim3 rg(HP / 4, NB * OC);
    k_resize<<<rg, rb>>>(out);
}